// round 10
// baseline (speedup 1.0000x reference)
#include <cuda_runtime.h>
#include <cstdint>

// NeuralHashVoxel: 32^3-Morton counting-sorted queries + per-level hash probing.
// Levels 0-1 (scattered lanes): 4-4 validity-gated probing (E[probes]=5.64).
// Levels 2-5 (post-sort coalesced): single-round 8-probe.
// Pipeline: 4 launches (hist, scan, scatter, nhv). g_hist starts zeroed (.bss)
// and nhv re-zeros it at the end of every call, so each graph replay sees zeros.
//
// Inputs: d_in[0] query_points f32 (N,3) in [0,50); d_in[1] features f32 (6,524288,8);
//         d_in[2] feature_indexs i32 (6,4194304) (-1 empty else [0,T)).
// Output: f32 (N,8).

#define NHV_L 6
#define NHV_T 524288
#define NHV_B 4194304u
#define NHV_BMASK 4194303u
#define P0 73856093u
#define P1 19349669u
#define P2 83492791u

#define NQ_MAX (1u << 20)
#define GRID1D 32
#define NBINS (GRID1D * GRID1D * GRID1D)     // 32768
#define SCAN_BLOCK_BINS 1024
#define SCAN_NBLK (NBINS / SCAN_BLOCK_BINS)  // 32

__device__ uint32_t g_hist[NBINS];
__device__ uint32_t g_blocksum[SCAN_NBLK];
__device__ uint32_t g_bsum_prefix[SCAN_NBLK];  // exclusive prefix of g_blocksum
__device__ uint32_t g_done_counter;
__device__ float4   g_qsort[NQ_MAX];           // xyz = point, w = orig index bits

static __device__ __forceinline__ uint32_t expand3(uint32_t x) {
    x &= 0x3FFu;
    x = (x | (x << 16)) & 0x030000FFu;
    x = (x | (x << 8))  & 0x0300F00Fu;
    x = (x | (x << 4))  & 0x030C30C3u;
    x = (x | (x << 2))  & 0x09249249u;
    return x;
}

static __device__ __forceinline__ uint32_t bin_of(float x, float y, float z) {
    const float sc = (float)GRID1D / 50.0f;
    int bx = (int)(x * sc), by = (int)(y * sc), bz = (int)(z * sc);
    bx = min(max(bx, 0), GRID1D - 1);
    by = min(max(by, 0), GRID1D - 1);
    bz = min(max(bz, 0), GRID1D - 1);
    return expand3((uint32_t)bx) | (expand3((uint32_t)by) << 1) | (expand3((uint32_t)bz) << 2);
}

__global__ void hist_kernel(const float* __restrict__ qp, int n) {
    int i = blockIdx.x * blockDim.x + threadIdx.x;
    if (i >= n) return;
    float x = qp[3 * i], y = qp[3 * i + 1], z = qp[3 * i + 2];
    atomicAdd(&g_hist[bin_of(x, y, z)], 1u);
}

// Per-superblock (1024 bins) exclusive scan; the LAST block to finish also
// computes the exclusive prefix over the 32 superblock sums.
__global__ void __launch_bounds__(SCAN_BLOCK_BINS) scan_blocks_kernel() {
    __shared__ uint32_t sh[SCAN_BLOCK_BINS];
    __shared__ int is_last;
    int t = threadIdx.x;
    int b = blockIdx.x * SCAN_BLOCK_BINS + t;
    uint32_t v = g_hist[b];
    sh[t] = v;
    __syncthreads();
    #pragma unroll
    for (int off = 1; off < SCAN_BLOCK_BINS; off <<= 1) {
        uint32_t add = (t >= off) ? sh[t - off] : 0u;
        __syncthreads();
        sh[t] += add;
        __syncthreads();
    }
    g_hist[b] = sh[t] - v;  // exclusive within superblock

    // Writer of g_blocksum fences + signals (store->fence->atomic, same thread).
    if (t == SCAN_BLOCK_BINS - 1) {
        g_blocksum[blockIdx.x] = sh[t];
        __threadfence();
        is_last = (atomicAdd(&g_done_counter, 1u) == (uint32_t)(SCAN_NBLK - 1));
    }
    __syncthreads();
    if (is_last) {
        __shared__ uint32_t bs[SCAN_NBLK];
        if (t < SCAN_NBLK) bs[t] = g_blocksum[t];
        __syncthreads();
        #pragma unroll
        for (int off = 1; off < SCAN_NBLK; off <<= 1) {
            uint32_t add = (t < SCAN_NBLK && t >= off) ? bs[t - off] : 0u;
            __syncthreads();
            if (t < SCAN_NBLK) bs[t] += add;
            __syncthreads();
        }
        if (t < SCAN_NBLK) g_bsum_prefix[t] = bs[t] - g_blocksum[t];  // exclusive
    }
}

__global__ void scatter_kernel(const float* __restrict__ qp, int n) {
    int i = blockIdx.x * blockDim.x + threadIdx.x;
    if (i >= n) return;
    float x = qp[3 * i], y = qp[3 * i + 1], z = qp[3 * i + 2];
    uint32_t bin = bin_of(x, y, z);
    uint32_t pos = atomicAdd(&g_hist[bin], 1u) + __ldg(&g_bsum_prefix[bin >> 10]);
    g_qsort[pos] = make_float4(x, y, z, __int_as_float(i));
}

static __device__ __forceinline__ int probe(const int* __restrict__ htab,
                                            uint32_t key) {
    return __ldg(htab + (key & NHV_BMASK));
}

// One resolution level. GATE: probe 4 corners, test, then the other 4
// (pays only when lanes are spatially scattered, i.e. fine levels).
template <bool GATE>
static __device__ __forceinline__ void do_level(
    float sx, float sy, float sz,
    const int* __restrict__ htab,
    const float* __restrict__ ftab,
    float* __restrict__ acc)
{
    const float bx = floorf(sx), by = floorf(sy), bz = floorf(sz);
    const float tx = sx - bx, ty = sy - by, tz = sz - bz;

    const uint32_t ix = (uint32_t)(int)bx;
    const uint32_t iy = (uint32_t)(int)by;
    const uint32_t iz = (uint32_t)(int)bz;
    const uint32_t h0 = ix * P0 + iy * P1 + iz * P2;

    // corner k: key = h0 + (k&4 ? P0) + (k&2 ? P1) + (k&1 ? P2)
    int idx[8];
    if (GATE) {
        idx[0] = probe(htab, h0);
        idx[1] = probe(htab, h0 + P2);
        idx[2] = probe(htab, h0 + P1);
        idx[3] = probe(htab, h0 + P1 + P2);
        if ((idx[0] | idx[1] | idx[2] | idx[3]) < 0) return;
        idx[4] = probe(htab, h0 + P0);
        idx[5] = probe(htab, h0 + P0 + P2);
        idx[6] = probe(htab, h0 + P0 + P1);
        idx[7] = probe(htab, h0 + P0 + P1 + P2);
        if ((idx[4] | idx[5] | idx[6] | idx[7]) < 0) return;
    } else {
        #pragma unroll
        for (int k = 0; k < 8; k++) {
            uint32_t key = h0;
            if (k & 4) key += P0;
            if (k & 2) key += P1;
            if (k & 1) key += P2;
            idx[k] = probe(htab, key);
        }
        if ((idx[0] | idx[1] | idx[2] | idx[3] |
             idx[4] | idx[5] | idx[6] | idx[7]) < 0) return;
    }

    const float wxa[2] = { 1.f - tx, tx };
    const float wya[2] = { 1.f - ty, ty };
    const float wza[2] = { 1.f - tz, tz };

    #pragma unroll
    for (int k = 0; k < 8; k++) {
        const float w = wxa[(k >> 2) & 1] * wya[(k >> 1) & 1] * wza[k & 1];
        uint32_t id = (uint32_t)idx[k];
        id = (id < NHV_T) ? id : (NHV_T - 1u);
        const float4* fp = (const float4*)(ftab + ((size_t)id << 3));
        float4 a = __ldg(fp);
        float4 b = __ldg(fp + 1);
        acc[0] = fmaf(w, a.x, acc[0]);
        acc[1] = fmaf(w, a.y, acc[1]);
        acc[2] = fmaf(w, a.z, acc[2]);
        acc[3] = fmaf(w, a.w, acc[3]);
        acc[4] = fmaf(w, b.x, acc[4]);
        acc[5] = fmaf(w, b.y, acc[5]);
        acc[6] = fmaf(w, b.z, acc[6]);
        acc[7] = fmaf(w, b.w, acc[7]);
    }
}

__global__ void __launch_bounds__(256) nhv_kernel(
    const float* __restrict__ feats,
    const int*   __restrict__ fidx,
    float* __restrict__ out,
    int n_query)
{
    int i = blockIdx.x * blockDim.x + threadIdx.x;

    // Tail duty: re-zero sort state for the NEXT call/replay (safe: this kernel
    // runs after scatter; .bss guarantees zeros on the very first call).
    {
        int z = blockIdx.x * blockDim.x + threadIdx.x;
        if (z < NBINS) g_hist[z] = 0u;
        if (z == 0) g_done_counter = 0u;
    }

    if (i >= n_query) return;

    const float4 q = g_qsort[i];
    const uint32_t n = (uint32_t)__float_as_int(q.w);

    float acc[8] = {0.f, 0.f, 0.f, 0.f, 0.f, 0.f, 0.f, 0.f};

    const size_t HB = (size_t)NHV_B;
    const size_t FT = (size_t)NHV_T * 8;

    // lev 0..5, scale = 4 / 2^lev; GATE only on the scattered fine levels.
    do_level<true >(q.x * 4.f,    q.y * 4.f,    q.z * 4.f,    fidx,          feats,          acc);
    do_level<true >(q.x * 2.f,    q.y * 2.f,    q.z * 2.f,    fidx + HB,     feats + FT,     acc);
    do_level<false>(q.x * 1.f,    q.y * 1.f,    q.z * 1.f,    fidx + 2*HB,   feats + 2*FT,   acc);
    do_level<false>(q.x * 0.5f,   q.y * 0.5f,   q.z * 0.5f,   fidx + 3*HB,   feats + 3*FT,   acc);
    do_level<false>(q.x * 0.25f,  q.y * 0.25f,  q.z * 0.25f,  fidx + 4*HB,   feats + 4*FT,   acc);
    do_level<false>(q.x * 0.125f, q.y * 0.125f, q.z * 0.125f, fidx + 5*HB,   feats + 5*FT,   acc);

    float4* o = (float4*)(out + ((size_t)n << 3));
    o[0] = make_float4(acc[0], acc[1], acc[2], acc[3]);
    o[1] = make_float4(acc[4], acc[5], acc[6], acc[7]);
}

extern "C" void kernel_launch(void* const* d_in, const int* in_sizes, int n_in,
                              void* d_out, int out_size)
{
    const float* qp    = (const float*)d_in[0];
    const float* feats = (const float*)d_in[1];
    const int*   fidx  = (const int*)d_in[2];
    float* out = (float*)d_out;

    int n_query = in_sizes[0] / 3;
    int threads = 256;
    int blocks = (n_query + threads - 1) / threads;

    hist_kernel<<<blocks, threads>>>(qp, n_query);
    scan_blocks_kernel<<<SCAN_NBLK, SCAN_BLOCK_BINS>>>();
    scatter_kernel<<<blocks, threads>>>(qp, n_query);
    nhv_kernel<<<blocks, threads>>>(feats, fidx, out, n_query);
}

// round 11
// speedup vs baseline: 1.0755x; 1.0755x over previous
#include <cuda_runtime.h>
#include <cstdint>

// NeuralHashVoxel: 64^3-Morton counting-sorted queries + per-level hash probing.
// Levels 0-1 (scattered lanes): 4-4 validity-gated probing (E[probes]=5.64).
// Levels 2-5 (post-sort coalesced): single-round 8-probe.
// Pipeline: 4 launches (hist, scan, scatter, nhv). g_hist starts zeroed (.bss)
// and nhv re-zeros it in its tail, so every graph replay sees zeros.
// [R10 lesson: 32^3 bins degrade nhv L1 locality (94 vs 89 us) -> 64^3 locked.]
//
// Inputs: d_in[0] query_points f32 (N,3) in [0,50); d_in[1] features f32 (6,524288,8);
//         d_in[2] feature_indexs i32 (6,4194304) (-1 empty else [0,T)).
// Output: f32 (N,8).

#define NHV_L 6
#define NHV_T 524288
#define NHV_B 4194304u
#define NHV_BMASK 4194303u
#define P0 73856093u
#define P1 19349669u
#define P2 83492791u

#define NQ_MAX (1u << 20)
#define GRID1D 64
#define NBINS (GRID1D * GRID1D * GRID1D)     // 262144
#define SCAN_BLOCK_BINS 1024
#define SCAN_NBLK (NBINS / SCAN_BLOCK_BINS)  // 256

__device__ uint32_t g_hist[NBINS];
__device__ uint32_t g_blocksum[SCAN_NBLK];
__device__ uint32_t g_bsum_prefix[SCAN_NBLK];  // exclusive prefix of g_blocksum
__device__ uint32_t g_done_counter;
__device__ float4   g_qsort[NQ_MAX];           // xyz = point, w = orig index bits

static __device__ __forceinline__ uint32_t expand3(uint32_t x) {
    x &= 0x3FFu;
    x = (x | (x << 16)) & 0x030000FFu;
    x = (x | (x << 8))  & 0x0300F00Fu;
    x = (x | (x << 4))  & 0x030C30C3u;
    x = (x | (x << 2))  & 0x09249249u;
    return x;
}

static __device__ __forceinline__ uint32_t bin_of(float x, float y, float z) {
    const float sc = (float)GRID1D / 50.0f;
    int bx = (int)(x * sc), by = (int)(y * sc), bz = (int)(z * sc);
    bx = min(max(bx, 0), GRID1D - 1);
    by = min(max(by, 0), GRID1D - 1);
    bz = min(max(bz, 0), GRID1D - 1);
    return expand3((uint32_t)bx) | (expand3((uint32_t)by) << 1) | (expand3((uint32_t)bz) << 2);
}

__global__ void hist_kernel(const float* __restrict__ qp, int n) {
    int i = blockIdx.x * blockDim.x + threadIdx.x;
    if (i >= n) return;
    float x = qp[3 * i], y = qp[3 * i + 1], z = qp[3 * i + 2];
    atomicAdd(&g_hist[bin_of(x, y, z)], 1u);
}

// Per-superblock (1024 bins) exclusive scan; the LAST block to finish also
// computes the exclusive prefix over the 256 superblock sums.
__global__ void __launch_bounds__(SCAN_BLOCK_BINS) scan_blocks_kernel() {
    __shared__ uint32_t sh[SCAN_BLOCK_BINS];
    __shared__ int is_last;
    int t = threadIdx.x;
    int b = blockIdx.x * SCAN_BLOCK_BINS + t;
    uint32_t v = g_hist[b];
    sh[t] = v;
    __syncthreads();
    #pragma unroll
    for (int off = 1; off < SCAN_BLOCK_BINS; off <<= 1) {
        uint32_t add = (t >= off) ? sh[t - off] : 0u;
        __syncthreads();
        sh[t] += add;
        __syncthreads();
    }
    g_hist[b] = sh[t] - v;  // exclusive within superblock

    // Writer of g_blocksum fences + signals (store->fence->atomic, same thread).
    if (t == SCAN_BLOCK_BINS - 1) {
        g_blocksum[blockIdx.x] = sh[t];
        __threadfence();
        is_last = (atomicAdd(&g_done_counter, 1u) == (uint32_t)(SCAN_NBLK - 1));
    }
    __syncthreads();
    if (is_last) {
        __shared__ uint32_t bs[SCAN_NBLK];
        if (t < SCAN_NBLK) bs[t] = g_blocksum[t];
        __syncthreads();
        #pragma unroll
        for (int off = 1; off < SCAN_NBLK; off <<= 1) {
            uint32_t add = (t < SCAN_NBLK && t >= off) ? bs[t - off] : 0u;
            __syncthreads();
            if (t < SCAN_NBLK) bs[t] += add;
            __syncthreads();
        }
        if (t < SCAN_NBLK) g_bsum_prefix[t] = bs[t] - g_blocksum[t];  // exclusive
    }
}

__global__ void scatter_kernel(const float* __restrict__ qp, int n) {
    int i = blockIdx.x * blockDim.x + threadIdx.x;
    if (i >= n) return;
    float x = qp[3 * i], y = qp[3 * i + 1], z = qp[3 * i + 2];
    uint32_t bin = bin_of(x, y, z);
    uint32_t pos = atomicAdd(&g_hist[bin], 1u) + __ldg(&g_bsum_prefix[bin >> 10]);
    g_qsort[pos] = make_float4(x, y, z, __int_as_float(i));
}

static __device__ __forceinline__ int probe(const int* __restrict__ htab,
                                            uint32_t key) {
    return __ldg(htab + (key & NHV_BMASK));
}

// One resolution level. GATE: probe 4 corners, test, then the other 4
// (pays only when lanes are spatially scattered, i.e. fine levels).
template <bool GATE>
static __device__ __forceinline__ void do_level(
    float sx, float sy, float sz,
    const int* __restrict__ htab,
    const float* __restrict__ ftab,
    float* __restrict__ acc)
{
    const float bx = floorf(sx), by = floorf(sy), bz = floorf(sz);
    const float tx = sx - bx, ty = sy - by, tz = sz - bz;

    const uint32_t ix = (uint32_t)(int)bx;
    const uint32_t iy = (uint32_t)(int)by;
    const uint32_t iz = (uint32_t)(int)bz;
    const uint32_t h0 = ix * P0 + iy * P1 + iz * P2;

    // corner k: key = h0 + (k&4 ? P0) + (k&2 ? P1) + (k&1 ? P2)
    int idx[8];
    if (GATE) {
        idx[0] = probe(htab, h0);
        idx[1] = probe(htab, h0 + P2);
        idx[2] = probe(htab, h0 + P1);
        idx[3] = probe(htab, h0 + P1 + P2);
        if ((idx[0] | idx[1] | idx[2] | idx[3]) < 0) return;
        idx[4] = probe(htab, h0 + P0);
        idx[5] = probe(htab, h0 + P0 + P2);
        idx[6] = probe(htab, h0 + P0 + P1);
        idx[7] = probe(htab, h0 + P0 + P1 + P2);
        if ((idx[4] | idx[5] | idx[6] | idx[7]) < 0) return;
    } else {
        #pragma unroll
        for (int k = 0; k < 8; k++) {
            uint32_t key = h0;
            if (k & 4) key += P0;
            if (k & 2) key += P1;
            if (k & 1) key += P2;
            idx[k] = probe(htab, key);
        }
        if ((idx[0] | idx[1] | idx[2] | idx[3] |
             idx[4] | idx[5] | idx[6] | idx[7]) < 0) return;
    }

    const float wxa[2] = { 1.f - tx, tx };
    const float wya[2] = { 1.f - ty, ty };
    const float wza[2] = { 1.f - tz, tz };

    #pragma unroll
    for (int k = 0; k < 8; k++) {
        const float w = wxa[(k >> 2) & 1] * wya[(k >> 1) & 1] * wza[k & 1];
        uint32_t id = (uint32_t)idx[k];
        id = (id < NHV_T) ? id : (NHV_T - 1u);
        const float4* fp = (const float4*)(ftab + ((size_t)id << 3));
        float4 a = __ldg(fp);
        float4 b = __ldg(fp + 1);
        acc[0] = fmaf(w, a.x, acc[0]);
        acc[1] = fmaf(w, a.y, acc[1]);
        acc[2] = fmaf(w, a.z, acc[2]);
        acc[3] = fmaf(w, a.w, acc[3]);
        acc[4] = fmaf(w, b.x, acc[4]);
        acc[5] = fmaf(w, b.y, acc[5]);
        acc[6] = fmaf(w, b.z, acc[6]);
        acc[7] = fmaf(w, b.w, acc[7]);
    }
}

__global__ void __launch_bounds__(256) nhv_kernel(
    const float* __restrict__ feats,
    const int*   __restrict__ fidx,
    float* __restrict__ out,
    int n_query)
{
    int i = blockIdx.x * blockDim.x + threadIdx.x;

    // Tail duty: re-zero sort state for the NEXT call/replay (safe: this kernel
    // runs after scatter; .bss guarantees zeros on the very first call).
    if (i < NBINS) g_hist[i] = 0u;
    if (i == 0) g_done_counter = 0u;

    if (i >= n_query) return;

    const float4 q = g_qsort[i];
    const uint32_t n = (uint32_t)__float_as_int(q.w);

    float acc[8] = {0.f, 0.f, 0.f, 0.f, 0.f, 0.f, 0.f, 0.f};

    const size_t HB = (size_t)NHV_B;
    const size_t FT = (size_t)NHV_T * 8;

    // lev 0..5, scale = 4 / 2^lev; GATE only on the scattered fine levels.
    do_level<true >(q.x * 4.f,    q.y * 4.f,    q.z * 4.f,    fidx,          feats,          acc);
    do_level<true >(q.x * 2.f,    q.y * 2.f,    q.z * 2.f,    fidx + HB,     feats + FT,     acc);
    do_level<false>(q.x * 1.f,    q.y * 1.f,    q.z * 1.f,    fidx + 2*HB,   feats + 2*FT,   acc);
    do_level<false>(q.x * 0.5f,   q.y * 0.5f,   q.z * 0.5f,   fidx + 3*HB,   feats + 3*FT,   acc);
    do_level<false>(q.x * 0.25f,  q.y * 0.25f,  q.z * 0.25f,  fidx + 4*HB,   feats + 4*FT,   acc);
    do_level<false>(q.x * 0.125f, q.y * 0.125f, q.z * 0.125f, fidx + 5*HB,   feats + 5*FT,   acc);

    float4* o = (float4*)(out + ((size_t)n << 3));
    o[0] = make_float4(acc[0], acc[1], acc[2], acc[3]);
    o[1] = make_float4(acc[4], acc[5], acc[6], acc[7]);
}

extern "C" void kernel_launch(void* const* d_in, const int* in_sizes, int n_in,
                              void* d_out, int out_size)
{
    const float* qp    = (const float*)d_in[0];
    const float* feats = (const float*)d_in[1];
    const int*   fidx  = (const int*)d_in[2];
    float* out = (float*)d_out;

    int n_query = in_sizes[0] / 3;
    int threads = 256;
    int blocks = (n_query + threads - 1) / threads;

    hist_kernel<<<blocks, threads>>>(qp, n_query);
    scan_blocks_kernel<<<SCAN_NBLK, SCAN_BLOCK_BINS>>>();
    scatter_kernel<<<blocks, threads>>>(qp, n_query);
    nhv_kernel<<<blocks, threads>>>(feats, fidx, out, n_query);
}